// round 16
// baseline (speedup 1.0000x reference)
#include <cuda_runtime.h>
#include <math.h>

// Problem constants
#define B_  4
#define T_  2048
#define D_  2048
#define M_  (B_*T_)      // 8192 rows
#define N_  2048         // D_OUT
#define K_  (3*D_)       // 6144 concat-K
#define NC  8            // scan chunks
#define LCH (T_/NC)      // 256 steps per chunk

// -------- scratch (device globals: allowed; runtime alloc is not) --------
__device__ float g_integ[(size_t)M_ * D_];   // 64 MB
__device__ float g_deriv[(size_t)M_ * D_];   // 64 MB
__device__ float g_carry_s[B_*NC*D_];
__device__ float g_carry_d[B_*NC*D_];
__device__ float g_entry_s[B_*NC*D_];
__device__ float g_entry_d[B_*NC*D_];
__device__ float g_gates[M_*3];

__device__ __forceinline__ float sigmoidf_(float v){ return 1.0f/(1.0f+expf(-v)); }

// ===========================================================================
// Pass 1 / Pass 3: chunked EMA scan.
//   FINAL=0: zero-init local scan, emit end-of-chunk carries only.
//   FINAL=1: init from exact chunk-entry state, emit full integ/deriv.
// Thread = one (b, chunk, d). 65536 threads -> bandwidth-bound, unroll-4 MLP.
// ===========================================================================
template<int FINAL>
__global__ void scan_chunk_kernel(const float* __restrict__ x,
                                  const float* __restrict__ alpha_logit,
                                  const float* __restrict__ beta_logit)
{
    int d = blockIdx.x*blockDim.x + threadIdx.x;
    int c = blockIdx.y, b = blockIdx.z;
    float alpha = sigmoidf_(alpha_logit[d]);
    float beta  = sigmoidf_(beta_logit[d]);
    float ia = 1.0f - alpha, ib = 1.0f - beta;
    int t0 = c*LCH;
    size_t base = ((size_t)b*T_ + t0)*D_ + d;
    const float* xp = x + base;
    int o = (b*NC + c)*D_ + d;

    float s, dv;
    if (FINAL) { s = g_entry_s[o]; dv = g_entry_d[o]; }
    else       { s = 0.0f;         dv = 0.0f; }
    float xprev = (t0 == 0) ? 0.0f : xp[-D_];

    float* ip = g_integ + base;
    float* dp = g_deriv + base;

    #pragma unroll 1
    for (int j = 0; j < LCH; j += 4) {
        float xv[4];
        #pragma unroll
        for (int u = 0; u < 4; u++) xv[u] = xp[(size_t)(j+u)*D_];
        #pragma unroll
        for (int u = 0; u < 4; u++) {
            s  = alpha*s + ia*xv[u];
            dv = beta*dv + ib*(xv[u] - xprev);
            xprev = xv[u];
            if (FINAL) {
                ip[(size_t)(j+u)*D_] = s;
                dp[(size_t)(j+u)*D_] = dv;
            }
        }
    }
    if (!FINAL) { g_carry_s[o] = s; g_carry_d[o] = dv; }
}

// ===========================================================================
// Pass 2: combine chunk carries sequentially (tiny).
// end_of_chunk = alpha^L * entry + local_end  =>  prefix over NC chunks.
// ===========================================================================
__global__ void scan_combine_kernel(const float* __restrict__ alpha_logit,
                                    const float* __restrict__ beta_logit)
{
    int d = blockIdx.x*blockDim.x + threadIdx.x;
    int b = blockIdx.y;
    float alpha = sigmoidf_(alpha_logit[d]);
    float beta  = sigmoidf_(beta_logit[d]);
    float aL = powf(alpha, (float)LCH);
    float bL = powf(beta,  (float)LCH);
    float s = 0.0f, dv = 0.0f;
    #pragma unroll
    for (int c = 0; c < NC; c++) {
        int o = (b*NC + c)*D_ + d;
        g_entry_s[o] = s;
        g_entry_d[o] = dv;
        s  = aL*s  + g_carry_s[o];
        dv = bL*dv + g_carry_d[o];
    }
}

// ===========================================================================
// Gates: warp-per-row. logits[g] = <x,Wg[g,0:D]> + <i,Wg[g,D:2D]> + <d,Wg[g,2D:3D]>
// then softmax over 3. W_gate (73KB) stays L1-resident per SM.
// ===========================================================================
__global__ void gates_kernel(const float* __restrict__ x,
                             const float* __restrict__ Wg,
                             const float* __restrict__ gbias)
{
    int m    = (int)((blockIdx.x*blockDim.x + threadIdx.x) >> 5);
    int lane = threadIdx.x & 31;
    if (m >= M_) return;
    const float4* xr = (const float4*)(x       + (size_t)m*D_);
    const float4* ir = (const float4*)(g_integ + (size_t)m*D_);
    const float4* dr = (const float4*)(g_deriv + (size_t)m*D_);
    float acc[3] = {0.f, 0.f, 0.f};
    for (int k = lane; k < D_/4; k += 32) {
        float4 xv = xr[k], iv = ir[k], dvv = dr[k];
        #pragma unroll
        for (int g = 0; g < 3; g++) {
            const float4* w = (const float4*)(Wg + (size_t)g*K_);
            float4 wx = w[k];
            float4 wi = w[D_/4 + k];
            float4 wd = w[2*(D_/4) + k];
            acc[g] += xv.x*wx.x + xv.y*wx.y + xv.z*wx.z + xv.w*wx.w
                    + iv.x*wi.x + iv.y*wi.y + iv.z*wi.z + iv.w*wi.w
                    + dvv.x*wd.x + dvv.y*wd.y + dvv.z*wd.z + dvv.w*wd.w;
        }
    }
    #pragma unroll
    for (int g = 0; g < 3; g++)
        #pragma unroll
        for (int off = 16; off; off >>= 1)
            acc[g] += __shfl_xor_sync(0xFFFFFFFFu, acc[g], off);
    if (lane == 0) {
        float l0 = acc[0] + gbias[0];
        float l1 = acc[1] + gbias[1];
        float l2 = acc[2] + gbias[2];
        float mx = fmaxf(l0, fmaxf(l1, l2));
        float e0 = expf(l0-mx), e1 = expf(l1-mx), e2 = expf(l2-mx);
        float inv = 1.0f/(e0+e1+e2);
        g_gates[m*3+0] = e0*inv;
        g_gates[m*3+1] = e1*inv;
        g_gates[m*3+2] = e2*inv;
    }
}

// ===========================================================================
// Fused GEMM: y[m,n] = sum_k A[m,k]*Wcat[n,k] + bias[n]
//   A[m,k]    = gates[m,seg]*src_seg[m,k']   (seg = k>>11, virtual, scaled at load)
//   Wcat[n,k] = {W_p,W_i,W_d}[n,k']
// 128x128x16 tile, 8x8/thread, A stored as duplicated {a,a} float2 so the
// inner product runs on packed fma.rn.f32x2 (2 FMA/instr on sm_103a).
// ===========================================================================
#define BM 128
#define BN 128
#define BK 16
#define TM 8
#define TN 8
#define NKT (K_/BK)

#define FMA2(d,a,b) asm("fma.rn.f32x2 %0, %1, %2, %0;" : "+l"(d) : "l"(a), "l"(b))

#define LOADT(kt) { \
    int k0 = (kt)*BK, seg = k0 >> 11, ks = k0 & 2047; \
    const float* Asrc = (seg==0) ? x  : ((seg==1) ? g_integ : g_deriv); \
    const float* Bsrc = (seg==0) ? Wp : ((seg==1) ? Wi      : Wd); \
    _Pragma("unroll") \
    for (int h = 0; h < 2; h++) { \
        int f = tid + h*256, row = f >> 2, quad = f & 3; \
        ra[h] = *(const float4*)(Asrc + (size_t)(m0+row)*D_ + (ks + quad*4)); \
        ga[h] = g_gates[(m0+row)*3 + seg]; \
        rb[h] = *(const float4*)(Bsrc + (size_t)(n0+row)*D_ + (ks + quad*4)); \
    } }

#define STORET() { \
    _Pragma("unroll") \
    for (int h = 0; h < 2; h++) { \
        int f = tid + h*256, row = f >> 2, quad = f & 3; \
        float g = ga[h]; float4 a = ra[h]; float4 bv = rb[h]; \
        As[quad*4+0][row] = make_float2(a.x*g, a.x*g); \
        As[quad*4+1][row] = make_float2(a.y*g, a.y*g); \
        As[quad*4+2][row] = make_float2(a.z*g, a.z*g); \
        As[quad*4+3][row] = make_float2(a.w*g, a.w*g); \
        Bs[quad*4+0][row] = bv.x; \
        Bs[quad*4+1][row] = bv.y; \
        Bs[quad*4+2][row] = bv.z; \
        Bs[quad*4+3][row] = bv.w; \
    } }

#define COMPUTET() { \
    _Pragma("unroll") \
    for (int k = 0; k < BK; k++) { \
        unsigned long long af[TM], bf[TN/2]; \
        const unsigned long long* ap = (const unsigned long long*)&As[k][ty*TM]; \
        const unsigned long long* bp = (const unsigned long long*)&Bs[k][tx*TN]; \
        _Pragma("unroll") for (int i = 0; i < TM;  i++) af[i] = ap[i]; \
        _Pragma("unroll") for (int j = 0; j < TN/2; j++) bf[j] = bp[j]; \
        _Pragma("unroll") \
        for (int i = 0; i < TM; i++) { \
            _Pragma("unroll") \
            for (int j = 0; j < TN/2; j++) FMA2(acc[i][j], af[i], bf[j]); \
        } \
    } }

__global__ void __launch_bounds__(256) gemm_kernel(
    const float* __restrict__ x,
    const float* __restrict__ Wp,
    const float* __restrict__ Wi,
    const float* __restrict__ Wd,
    const float* __restrict__ bias,
    float* __restrict__ y)
{
    __shared__ __align__(16) float2 As[BK][BM];   // duplicated-pair A fragments
    __shared__ __align__(16) float  Bs[BK][BN];

    const int tid  = threadIdx.x;
    const int m0   = blockIdx.y * BM;
    const int n0   = blockIdx.x * BN;
    const int w    = tid >> 5, lane = tid & 31;
    // warp-internal 8x4 lane tiling: B-fragment LDS conflicts drop to 2-way,
    // A-fragment loads become 4-address broadcasts.
    const int tx = (w & 1)*8 + (lane & 7);
    const int ty = (w >> 1)*4 + (lane >> 3);

    unsigned long long acc[TM][TN/2];
    #pragma unroll
    for (int i = 0; i < TM; i++)
        #pragma unroll
        for (int j = 0; j < TN/2; j++) acc[i][j] = 0ull;

    float4 ra[2], rb[2];
    float  ga[2];

    LOADT(0);
    STORET();
    __syncthreads();

    for (int kt = 1; kt < NKT; kt++) {
        LOADT(kt);            // global prefetch of next tile (regs)
        COMPUTET();           // compute on current smem tile
        __syncthreads();
        STORET();             // regs -> smem
        __syncthreads();
    }
    COMPUTET();

    // epilogue: unpack packed pairs, add bias, vectorized store
    float bs[TN];
    #pragma unroll
    for (int j = 0; j < TN; j++) bs[j] = bias[n0 + tx*TN + j];
    #pragma unroll
    for (int i = 0; i < TM; i++) {
        int row = m0 + ty*TM + i;
        float out[TN];
        #pragma unroll
        for (int j = 0; j < TN/2; j++) {
            float2 p = *reinterpret_cast<float2*>(&acc[i][j]);
            out[2*j]   = p.x + bs[2*j];
            out[2*j+1] = p.y + bs[2*j+1];
        }
        float* yp = y + (size_t)row*N_ + n0 + tx*TN;
        *(float4*)(yp)     = make_float4(out[0], out[1], out[2], out[3]);
        *(float4*)(yp + 4) = make_float4(out[4], out[5], out[6], out[7]);
    }
}

// ===========================================================================
// launch
// inputs (metadata order): x, W_p, W_i, W_d, alpha_logit, beta_logit,
//                          W_gate_w, W_gate_b, bias
// ===========================================================================
extern "C" void kernel_launch(void* const* d_in, const int* in_sizes, int n_in,
                              void* d_out, int out_size)
{
    (void)in_sizes; (void)n_in; (void)out_size;
    const float* x    = (const float*)d_in[0];
    const float* Wp   = (const float*)d_in[1];
    const float* Wi   = (const float*)d_in[2];
    const float* Wd   = (const float*)d_in[3];
    const float* al   = (const float*)d_in[4];
    const float* bl   = (const float*)d_in[5];
    const float* Wg   = (const float*)d_in[6];
    const float* gb   = (const float*)d_in[7];
    const float* bias = (const float*)d_in[8];
    float* y = (float*)d_out;

    dim3 gscan(D_/256, NC, B_);
    scan_chunk_kernel<0><<<gscan, 256>>>(x, al, bl);
    scan_combine_kernel<<<dim3(D_/256, B_), 256>>>(al, bl);
    scan_chunk_kernel<1><<<gscan, 256>>>(x, al, bl);
    gates_kernel<<<M_/8, 256>>>(x, Wg, gb);
    gemm_kernel<<<dim3(N_/BN, M_/BM), 256>>>(x, Wp, Wi, Wd, bias, y);
}